// round 11
// baseline (speedup 1.0000x reference)
#include <cuda_runtime.h>
#include <cstdint>

// Problem constants
#define BB   64
#define TT   2048
#define II   200
#define HH   100
#define G4   400   // 4*H

// Scratch: xg[t][b][j] (t-major so scan streams coalesced rows), ~210MB.
__device__ float g_xg[(size_t)TT * BB * G4];

// ---- packed fp32x2 helpers ---------------------------------------------
union f2u { float2 f; unsigned long long u; };
union f4u { float4 f; ulonglong2 u; };

__device__ __forceinline__ unsigned long long ffma2(unsigned long long a,
                                                    unsigned long long b,
                                                    unsigned long long c) {
    unsigned long long d;
    asm("fma.rn.f32x2 %0, %1, %2, %3;" : "=l"(d) : "l"(a), "l"(b), "l"(c));
    return d;
}
__device__ __forceinline__ float tanh_mufu(float x) {
    float t;
    asm("tanh.approx.f32 %0, %1;" : "=f"(t) : "f"(x));
    return t;
}
// branch-free activation: is_t -> tanh, else sigmoid = 0.5*tanh(x/2)+0.5
__device__ __forceinline__ float act_(float x, bool is_t) {
    float xx = is_t ? x : 0.5f * x;
    float t  = tanh_mufu(xx);
    return is_t ? t : fmaf(0.5f, t, 0.5f);
}

// ---- kernel 1: input projection (register-blocked SIMT GEMM) -----------
// C[131072, 400] = x[131072, 200] @ W_ih^T  (+bias) -> g_xg[t][b][col]
// CTA tile: 64 rows x 100 cols (grid 2048 x 4). 200 threads, thread tile 8x4.
#define KC 20
#define AS_STRIDE 68   // 68*4=272B, 16B aligned

__global__ __launch_bounds__(200, 4)
void proj_kernel(const float* __restrict__ x,
                 const float* __restrict__ Wih,
                 const float* __restrict__ bih,
                 const float* __restrict__ bhh) {
    __shared__ float As[KC * AS_STRIDE];   // As[k][r], 5.44 KB
    __shared__ float Bs[KC * HH];          // Bs[k][jc], 8 KB

    const int tid  = threadIdx.x;
    const int tx   = tid % 25;             // col group: cols tx*4 .. tx*4+3
    const int ty   = tid / 25;             // row group: rows ty*8 .. ty*8+7
    const int row0 = blockIdx.x * 64;
    const int c0   = blockIdx.y * HH;      // global column base (0/100/200/300)

    unsigned long long acc[8][2];
    #pragma unroll
    for (int r = 0; r < 8; ++r) { acc[r][0] = 0ULL; acc[r][1] = 0ULL; }

    for (int cch = 0; cch < II / KC; ++cch) {
        const int k0 = cch * KC;
        __syncthreads();   // previous chunk fully consumed

        // Stage A: 64 rows x 20 k, transposed to As[k][r]. 320 float4 loads.
        for (int idx = tid; idx < 64 * (KC / 4); idx += 200) {
            int r = idx / (KC / 4);
            int q = idx - r * (KC / 4);
            float4 v = *(const float4*)&x[(size_t)(row0 + r) * II + k0 + 4 * q];
            As[(4 * q + 0) * AS_STRIDE + r] = v.x;
            As[(4 * q + 1) * AS_STRIDE + r] = v.y;
            As[(4 * q + 2) * AS_STRIDE + r] = v.z;
            As[(4 * q + 3) * AS_STRIDE + r] = v.w;
        }
        // Stage B (transposing): thread t<100 owns W_ih row j=c0+t (L2-resident)
        if (tid < HH) {
            const float* wrow = &Wih[(size_t)(c0 + tid) * II + k0];
            #pragma unroll
            for (int q = 0; q < KC / 4; ++q) {
                float4 v = *(const float4*)&wrow[4 * q];
                Bs[(4 * q + 0) * HH + tid] = v.x;
                Bs[(4 * q + 1) * HH + tid] = v.y;
                Bs[(4 * q + 2) * HH + tid] = v.z;
                Bs[(4 * q + 3) * HH + tid] = v.w;
            }
        }
        __syncthreads();

        #pragma unroll 4
        for (int k = 0; k < KC; ++k) {
            f4u a0, a1, w0;
            a0.f = *(const float4*)&As[k * AS_STRIDE + ty * 8];
            a1.f = *(const float4*)&As[k * AS_STRIDE + ty * 8 + 4];
            w0.f = *(const float4*)&Bs[k * HH + tx * 4];
            float ar[8] = {a0.f.x, a0.f.y, a0.f.z, a0.f.w,
                           a1.f.x, a1.f.y, a1.f.z, a1.f.w};
            #pragma unroll
            for (int r = 0; r < 8; ++r) {
                f2u av; av.f.x = ar[r]; av.f.y = ar[r];
                acc[r][0] = ffma2(av.u, w0.u.x, acc[r][0]);
                acc[r][1] = ffma2(av.u, w0.u.y, acc[r][1]);
            }
        }
    }

    // Epilogue: add bias, scatter rows to g_xg[t][b][col]
    const int col = c0 + tx * 4;
    f4u bi, bh;
    bi.f = *(const float4*)&bih[col];
    bh.f = *(const float4*)&bhh[col];
    float4 bias = make_float4(bi.f.x + bh.f.x, bi.f.y + bh.f.y,
                              bi.f.z + bh.f.z, bi.f.w + bh.f.w);

    #pragma unroll
    for (int r = 0; r < 8; ++r) {
        int m = row0 + ty * 8 + r;
        int b = m >> 11;           // m / 2048
        int t = m & 2047;
        f2u p0, p1;
        p0.u = acc[r][0]; p1.u = acc[r][1];
        float4 o = make_float4(p0.f.x + bias.x, p0.f.y + bias.y,
                               p1.f.x + bias.z, p1.f.y + bias.w);
        *(float4*)&g_xg[((size_t)t * BB + b) * G4 + col] = o;
    }
}

// ---- kernel 2: scan, 2 batches per CTA in DISJOINT WARP GROUPS ----------
// 32 CTAs x 832 threads. Group A = threads 0..415 (warps 0-12) handles
// batch 2*cta; group B = threads 416..831 (warps 13-25) handles batch
// 2*cta+1. Each group runs the R6-style quad-gate step (thread 4j..4j+3 =
// gates i,f,g,o of unit j) with its OWN named barrier (bar.sync 1/2, 416)
// and its own double-buffered h -> groups run out of phase and fill each
// other's stall bubbles. Per-thread instruction count unchanged vs R6.
// Threads with local tid >= 400 compute clamped duplicates, never store.
#define GT 416   // threads per group (13 warps)

__global__ __launch_bounds__(832, 1)
void scan_kernel(const float* __restrict__ Whh, float* __restrict__ out) {
    const int tid  = threadIdx.x;
    const int grp  = (tid >= GT);              // 0 = A, 1 = B
    const int ltid = grp ? (tid - GT) : tid;   // 0..415
    const int act  = (ltid < G4);              // active gate thread
    const int j    = act ? (ltid >> 2) : (HH - 1);   // clamped unit
    const int g    = ltid & 3;                 // gate: 0=i 1=f 2=g 3=o
    const int lane = tid & 31;
    const unsigned qmask = 0xFu << (lane & ~3);
    const int bidx = blockIdx.x * 2 + grp;     // this group's batch
    const int barid = grp + 1;                 // named barrier 1 or 2

    __shared__ __align__(16) float h_sh[2][2][HH];   // [phase][group][unit]

    // W_hh row (g*100 + j) in registers: 25 float4
    f4u wreg[HH / 4];
    const float4* wr = (const float4*)(Whh + (size_t)(g * HH + j) * HH);
    #pragma unroll
    for (int q = 0; q < HH / 4; ++q) wreg[q].f = wr[q];

    float c = 0.0f, hval = 0.0f;
    if (ltid < HH) h_sh[0][grp][ltid] = 0.0f;
    __syncthreads();   // once, before the loop (orders both groups' init)

    const float* xg = g_xg + (size_t)bidx * G4 + (g * HH + j);
    const size_t ts = (size_t)BB * G4;

    float cur0 = __ldcs(&xg[0]);
    float cur1 = __ldcs(&xg[ts]);

    int p = 0;
    for (int tg = 0; tg < TT; tg += 2) {
        // prefetch steps tg+2, tg+3 (consumed next group-iteration)
        int t2 = tg + 2; t2 = (t2 < TT) ? t2 : (TT - 1);
        int t3 = tg + 3; t3 = (t3 < TT) ? t3 : (TT - 1);
        float nxt0 = __ldcs(&xg[(size_t)t2 * ts]);
        float nxt1 = __ldcs(&xg[(size_t)t3 * ts]);

        #pragma unroll
        for (int i = 0; i < 2; ++i) {
            float xv = i ? cur1 : cur0;

            unsigned long long a0 = 0ULL, a1 = 0ULL;
            const float4* hb = (const float4*)h_sh[p][grp];
            #pragma unroll
            for (int q = 0; q < HH / 4; ++q) {
                f4u h4; h4.f = hb[q];            // broadcast LDS.128
                a0 = ffma2(wreg[q].u.x, h4.u.x, a0);
                a1 = ffma2(wreg[q].u.y, h4.u.y, a1);
            }
            f2u s0, s1; s0.u = a0; s1.u = a1;
            float gate = (s0.f.x + s0.f.y) + (s1.f.x + s1.f.y) + xv;

            const bool is_t = (g == 2);
            float a = act_(gate, is_t);

            // quad combine (independent shfls), leader-only tail
            float fg = __shfl_down_sync(qmask, a, 1, 4);
            float gg = __shfl_down_sync(qmask, a, 2, 4);
            float og = __shfl_down_sync(qmask, a, 3, 4);
            if (g == 0) {
                c    = fg * c + a * gg;
                hval = og * tanh_mufu(c);
                if (act) h_sh[p ^ 1][grp][j] = hval;   // write OTHER buffer
            }
            // group-private barrier: only this group's 13 warps
            asm volatile("bar.sync %0, %1;" :: "r"(barid), "n"(GT) : "memory");
            p ^= 1;
        }

        cur0 = nxt0;
        cur1 = nxt1;
    }

    if (g == 0 && act) out[bidx * HH + j] = hval;
}

// ---- launch ------------------------------------------------------------
extern "C" void kernel_launch(void* const* d_in, const int* in_sizes, int n_in,
                              void* d_out, int out_size) {
    const float* x   = (const float*)d_in[0];   // [64,2048,200]
    const float* Wih = (const float*)d_in[1];   // [400,200]
    const float* Whh = (const float*)d_in[2];   // [400,100]
    const float* bih = (const float*)d_in[3];   // [400]
    const float* bhh = (const float*)d_in[4];   // [400]
    float* out = (float*)d_out;                 // [64,100]

    proj_kernel<<<dim3(TT * BB / 64, 4), 200>>>(x, Wih, bih, bhh);
    scan_kernel<<<BB / 2, 832>>>(Whh, out);
}

// round 12
// speedup vs baseline: 4.0826x; 4.0826x over previous
#include <cuda_runtime.h>
#include <cstdint>

// Problem constants
#define BB   64
#define TT   2048
#define II   200
#define HH   100
#define G4   400   // 4*H

// Scratch: xg[t][b][j] (t-major so scan CTA b streams coalesced rows), ~210MB.
__device__ float g_xg[(size_t)TT * BB * G4];

// ---- packed fp32x2 helpers ---------------------------------------------
union f2u { float2 f; unsigned long long u; };
union f4u { float4 f; ulonglong2 u; };

__device__ __forceinline__ unsigned long long ffma2(unsigned long long a,
                                                    unsigned long long b,
                                                    unsigned long long c) {
    unsigned long long d;
    asm("fma.rn.f32x2 %0, %1, %2, %3;" : "=l"(d) : "l"(a), "l"(b), "l"(c));
    return d;
}
__device__ __forceinline__ unsigned long long fadd2(unsigned long long a,
                                                    unsigned long long b) {
    unsigned long long d;
    asm("add.rn.f32x2 %0, %1, %2;" : "=l"(d) : "l"(a), "l"(b));
    return d;
}
__device__ __forceinline__ float tanh_mufu(float x) {
    float t;
    asm("tanh.approx.f32 %0, %1;" : "=f"(t) : "f"(x));
    return t;
}

// ---- kernel 1: input projection (register-blocked SIMT GEMM) -----------
// C[131072, 400] = x[131072, 200] @ W_ih^T  (+bias) -> g_xg[t][b][col]
// CTA tile: 64 rows x 100 cols (grid 2048 x 4). 200 threads, thread tile 8x4.
#define KC 20
#define AS_STRIDE 68   // 68*4=272B, 16B aligned

__global__ __launch_bounds__(200, 4)
void proj_kernel(const float* __restrict__ x,
                 const float* __restrict__ Wih,
                 const float* __restrict__ bih,
                 const float* __restrict__ bhh) {
    __shared__ float As[KC * AS_STRIDE];   // As[k][r], 5.44 KB
    __shared__ float Bs[KC * HH];          // Bs[k][jc], 8 KB

    const int tid  = threadIdx.x;
    const int tx   = tid % 25;             // col group: cols tx*4 .. tx*4+3
    const int ty   = tid / 25;             // row group: rows ty*8 .. ty*8+7
    const int row0 = blockIdx.x * 64;
    const int c0   = blockIdx.y * HH;      // global column base (0/100/200/300)

    unsigned long long acc[8][2];
    #pragma unroll
    for (int r = 0; r < 8; ++r) { acc[r][0] = 0ULL; acc[r][1] = 0ULL; }

    for (int cch = 0; cch < II / KC; ++cch) {
        const int k0 = cch * KC;
        __syncthreads();   // previous chunk fully consumed

        // Stage A: 64 rows x 20 k, transposed to As[k][r]. 320 float4 loads.
        for (int idx = tid; idx < 64 * (KC / 4); idx += 200) {
            int r = idx / (KC / 4);
            int q = idx - r * (KC / 4);
            float4 v = *(const float4*)&x[(size_t)(row0 + r) * II + k0 + 4 * q];
            As[(4 * q + 0) * AS_STRIDE + r] = v.x;
            As[(4 * q + 1) * AS_STRIDE + r] = v.y;
            As[(4 * q + 2) * AS_STRIDE + r] = v.z;
            As[(4 * q + 3) * AS_STRIDE + r] = v.w;
        }
        // Stage B (transposing): thread t<100 owns W_ih row j=c0+t (L2-resident)
        if (tid < HH) {
            const float* wrow = &Wih[(size_t)(c0 + tid) * II + k0];
            #pragma unroll
            for (int q = 0; q < KC / 4; ++q) {
                float4 v = *(const float4*)&wrow[4 * q];
                Bs[(4 * q + 0) * HH + tid] = v.x;
                Bs[(4 * q + 1) * HH + tid] = v.y;
                Bs[(4 * q + 2) * HH + tid] = v.z;
                Bs[(4 * q + 3) * HH + tid] = v.w;
            }
        }
        __syncthreads();

        #pragma unroll 4
        for (int k = 0; k < KC; ++k) {
            f4u a0, a1, w0;
            a0.f = *(const float4*)&As[k * AS_STRIDE + ty * 8];
            a1.f = *(const float4*)&As[k * AS_STRIDE + ty * 8 + 4];
            w0.f = *(const float4*)&Bs[k * HH + tx * 4];
            float ar[8] = {a0.f.x, a0.f.y, a0.f.z, a0.f.w,
                           a1.f.x, a1.f.y, a1.f.z, a1.f.w};
            #pragma unroll
            for (int r = 0; r < 8; ++r) {
                f2u av; av.f.x = ar[r]; av.f.y = ar[r];
                acc[r][0] = ffma2(av.u, w0.u.x, acc[r][0]);
                acc[r][1] = ffma2(av.u, w0.u.y, acc[r][1]);
            }
        }
    }

    // Epilogue: add bias, scatter rows to g_xg[t][b][col]
    const int col = c0 + tx * 4;
    f4u bi, bh;
    bi.f = *(const float4*)&bih[col];
    bh.f = *(const float4*)&bhh[col];
    float4 bias = make_float4(bi.f.x + bh.f.x, bi.f.y + bh.f.y,
                              bi.f.z + bh.f.z, bi.f.w + bh.f.w);

    #pragma unroll
    for (int r = 0; r < 8; ++r) {
        int m = row0 + ty * 8 + r;
        int b = m >> 11;           // m / 2048
        int t = m & 2047;
        f2u p0, p1;
        p0.u = acc[r][0]; p1.u = acc[r][1];
        float4 o = make_float4(p0.f.x + bias.x, p0.f.y + bias.y,
                               p1.f.x + bias.z, p1.f.y + bias.w);
        *(float4*)&g_xg[((size_t)t * BB + b) * G4 + col] = o;
    }
}

// ---- kernel 2: sequential LSTM scan (R6 structure + MUFU.TANH) ----------
// One CTA per batch row, 400 threads. Threads 4j..4j+3 own the i,f,g,o
// gates of hidden unit j (same quad) -> combine via quad shfl.
// h double-buffered (1 barrier/step). xg prefetched a FULL GROUP (4 steps)
// ahead via a register ring. Activations use MUFU.TANH (1 MUFU each):
// sigmoid(x) = 0.5*tanh(x/2)+0.5.
#define SG 4   // steps per prefetch group (TT % SG == 0)

__global__ __launch_bounds__(400, 1)
void scan_kernel(const float* __restrict__ Whh, float* __restrict__ out) {
    const int b    = blockIdx.x;
    const int tid  = threadIdx.x;
    const int j    = tid >> 2;     // hidden unit 0..99
    const int g    = tid & 3;      // gate: 0=i 1=f 2=g 3=o
    const unsigned qmask = 0xFu << ((tid & 31) & ~3);   // this thread's quad

    __shared__ __align__(16) float h_sh[2][HH];

    // W_hh row (g*100 + j), 100 floats -> 25 float4 in registers
    f4u wreg[HH / 4];
    const float4* wr = (const float4*)(Whh + (size_t)(g * HH + j) * HH);
    #pragma unroll
    for (int q = 0; q < HH / 4; ++q) wreg[q].f = wr[q];

    float c = 0.0f, hval = 0.0f;
    if (tid < HH) h_sh[0][tid] = 0.0f;
    __syncthreads();

    const float* xg = g_xg + (size_t)b * G4 + (g * HH + j);
    const size_t tstride = (size_t)BB * G4;

    float cur[SG], nxt[SG];
    #pragma unroll
    for (int i = 0; i < SG; ++i) cur[i] = __ldcs(&xg[(size_t)i * tstride]);

    int p = 0;
    for (int tg = 0; tg < TT; tg += SG) {
        // issue next group's loads NOW (consumed >= SG steps from now)
        #pragma unroll
        for (int i = 0; i < SG; ++i) {
            int tt = tg + SG + i;
            tt = (tt < TT) ? tt : (TT - 1);
            nxt[i] = __ldcs(&xg[(size_t)tt * tstride]);
        }

        #pragma unroll
        for (int i = 0; i < SG; ++i) {
            // 4 independent accumulation chains (depth ~13 each)
            unsigned long long a0 = 0ULL, a1 = 0ULL, a2 = 0ULL, a3 = 0ULL;
            const float4* hb = (const float4*)h_sh[p];
            #pragma unroll
            for (int q = 0; q < HH / 4; ++q) {
                f4u h4; h4.f = hb[q];            // broadcast LDS.128
                if (q & 1) {
                    a2 = ffma2(wreg[q].u.x, h4.u.x, a2);
                    a3 = ffma2(wreg[q].u.y, h4.u.y, a3);
                } else {
                    a0 = ffma2(wreg[q].u.x, h4.u.x, a0);
                    a1 = ffma2(wreg[q].u.y, h4.u.y, a1);
                }
            }
            f2u s0, s1;
            s0.u = fadd2(a0, a2);
            s1.u = fadd2(a1, a3);
            float gate = (s0.f.x + s0.f.y) + (s1.f.x + s1.f.y) + cur[i];

            // branch-free activation via MUFU.TANH:
            // g==2 -> tanh(gate); else sigmoid(gate) = 0.5*tanh(gate/2)+0.5
            bool is_t = (g == 2);
            float xx = is_t ? gate : 0.5f * gate;
            float th = tanh_mufu(xx);
            float a  = is_t ? th : fmaf(0.5f, th, 0.5f);

            // quad combine (lanes of this quad, all converged)
            float fg = __shfl_down_sync(qmask, a, 1, 4);
            float gg = __shfl_down_sync(qmask, a, 2, 4);
            float og = __shfl_down_sync(qmask, a, 3, 4);
            if (g == 0) {
                c    = fg * c + a * gg;
                hval = og * tanh_mufu(c);
                h_sh[p ^ 1][j] = hval;           // write OTHER buffer
            }
            __syncthreads();
            p ^= 1;
        }

        #pragma unroll
        for (int i = 0; i < SG; ++i) cur[i] = nxt[i];
    }

    if (g == 0) out[b * HH + j] = hval;
}

// ---- launch ------------------------------------------------------------
extern "C" void kernel_launch(void* const* d_in, const int* in_sizes, int n_in,
                              void* d_out, int out_size) {
    const float* x   = (const float*)d_in[0];   // [64,2048,200]
    const float* Wih = (const float*)d_in[1];   // [400,200]
    const float* Whh = (const float*)d_in[2];   // [400,100]
    const float* bih = (const float*)d_in[3];   // [400]
    const float* bhh = (const float*)d_in[4];   // [400]
    float* out = (float*)d_out;                 // [64,100]

    proj_kernel<<<dim3(TT * BB / 64, 4), 200>>>(x, Wih, bih, bhh);
    scan_kernel<<<BB, 400>>>(Whh, out);
}